// round 6
// baseline (speedup 1.0000x reference)
#include <cuda_runtime.h>
#include <math.h>

#define NN 50000
#define EE 400000
#define FF 32
#define HALF_E (EE / 2)
#define EPT 128          // edges per tile
#define EPAD 132         // padded edge stride in staged smem
#define NTILES (EE / EPT)
#define TBT 256          // threads per tile block

typedef unsigned long long ull;

// ---------------- scratch (static device arrays; allocation-free) ----------------
__device__ __align__(128) float g_e1[(size_t)EE * FF];
__device__ __align__(128) float g_e2[(size_t)EE * FF];
__device__ __align__(128) float g_e3[(size_t)EE * FF];
__device__ __align__(128) float g_acc1[(size_t)NN * FF];
__device__ __align__(128) float g_acc2[(size_t)NN * FF];
__device__ __align__(128) float g_acc3[(size_t)NN * FF];
__device__ __align__(128) float g_cnt[NN];

// ---------------- f32x2 helpers ----------------
__device__ __forceinline__ void ffma2(ull& d, ull a, ull b) {
    asm("fma.rn.f32x2 %0, %1, %2, %0;" : "+l"(d) : "l"(a), "l"(b));
}
__device__ __forceinline__ ull pk2(float v) {
    ull r;
    asm("mov.b64 %0, {%1, %1};" : "=l"(r) : "f"(v));
    return r;
}
union U2 {
    ull u;
    float f[2];
};
union V32 {
    float f[FF];
    ull u[FF / 2];
};

__device__ __forceinline__ void cpsh(float* dst, const float* src, int n, int tid, int nt) {
    for (int i = tid; i < n; i += nt) dst[i] = src[i];
}
__device__ __forceinline__ void red4(float* __restrict__ a, float x, float y, float z, float w) {
    asm volatile("red.global.add.v4.f32 [%0], {%1, %2, %3, %4};" ::"l"(a), "f"(x), "f"(y),
                 "f"(z), "f"(w)
                 : "memory");
}

// ---------------- tile staging ----------------
// stage a 32-wide segment into Xs rows [k0, k0+32); rows gathered via Is (or edge-major)
__device__ __forceinline__ void stage32(float* __restrict__ Xs, int k0,
                                        const float* __restrict__ src,
                                        const int* __restrict__ Is, int base, int tid) {
    int e = tid & 127;
    int kq0 = (tid >> 7) * 4;  // 0 or 4
    int row = Is ? Is[e] : (base + e);
    const float* sp = src + (size_t)row * FF;
#pragma unroll
    for (int it = 0; it < 4; it++) {
        int kq = kq0 + it;  // covers 0..7
        float4 v = *(const float4*)(sp + kq * 4);
        float* xp = Xs + (size_t)(k0 + kq * 4) * EPAD + e;
        xp[0 * EPAD] = v.x;
        xp[1 * EPAD] = v.y;
        xp[2 * EPAD] = v.z;
        xp[3 * EPAD] = v.w;
    }
}
// stage the 4-wide edge_attr segment into rows [k0, k0+4)
__device__ __forceinline__ void stage4(float* __restrict__ Xs, int k0,
                                       const float* __restrict__ ea, int base, int tid) {
    if (tid < 128) {
        int e = tid;
        float4 v = *(const float4*)(ea + (size_t)(base + e) * 4);
        Xs[(k0 + 0) * EPAD + e] = v.x;
        Xs[(k0 + 1) * EPAD + e] = v.y;
        Xs[(k0 + 2) * EPAD + e] = v.z;
        Xs[(k0 + 3) * EPAD + e] = v.w;
    }
}

// ---------------- tile GEMM: thread computes 4 edges x 4 cols ----------------
template <int K>
__device__ __forceinline__ void gemm_acc(const float* __restrict__ Xs,
                                         const float* __restrict__ Ws,
                                         const float* __restrict__ bs, int eg, int cg,
                                         ull acc[8]) {
    ull b0 = *(const ull*)(bs + cg * 4);
    ull b1 = *(const ull*)(bs + cg * 4 + 2);
#pragma unroll
    for (int e = 0; e < 4; e++) {
        acc[2 * e] = b0;
        acc[2 * e + 1] = b1;
    }
    const float* xp = Xs + eg * 4;
    const float* wp = Ws + cg * 4;
#pragma unroll 4
    for (int k = 0; k < K; k++) {
        float4 xv = *(const float4*)(xp + (size_t)k * EPAD);
        ulonglong2 w = *(const ulonglong2*)(wp + k * FF);
        ull v0 = pk2(xv.x), v1 = pk2(xv.y), v2 = pk2(xv.z), v3 = pk2(xv.w);
        ffma2(acc[0], v0, w.x);
        ffma2(acc[1], v0, w.y);
        ffma2(acc[2], v1, w.x);
        ffma2(acc[3], v1, w.y);
        ffma2(acc[4], v2, w.x);
        ffma2(acc[5], v2, w.y);
        ffma2(acc[6], v3, w.x);
        ffma2(acc[7], v3, w.y);
    }
}

// store acc (4e x 4c) into a k-major smem tile [32][EPAD], optional relu
__device__ __forceinline__ void store_kmajor(float* __restrict__ dst, const ull acc[8], int eg,
                                             int cg, bool relu) {
#pragma unroll
    for (int e = 0; e < 4; e++) {
#pragma unroll
        for (int j = 0; j < 4; j++) {
            U2 t;
            t.u = acc[2 * e + (j >> 1)];
            float v = t.f[j & 1];
            if (relu) v = fmaxf(v, 0.f);
            dst[(size_t)(cg * 4 + j) * EPAD + eg * 4 + e] = v;
        }
    }
}

// ---------------- init / finalize ----------------
__global__ void k_init(const float* __restrict__ beta, float* __restrict__ out) {
    int i = blockIdx.x * blockDim.x + threadIdx.x;
    if (i < NN * FF) {
        g_acc1[i] = 0.f;
        g_acc2[i] = 0.f;
        g_acc3[i] = 0.f;
    }
    if (i < NN) g_cnt[i] = 0.f;
    if (i < 3 * NN) out[(size_t)5 * EE + i] = beta[i];
}
__global__ void k_final(int which) {
    int i = blockIdx.x * blockDim.x + threadIdx.x;
    if (i >= NN * FF) return;
    float* acc = (which == 0) ? g_acc1 : (which == 1) ? g_acc2 : g_acc3;
    float c = fmaxf(g_cnt[i >> 5], 1.0f);
    acc[i] = fmaxf(acc[i] / c, 0.0f);
}

// ---------------- conv1 (pair kernel, proven) ----------------
__device__ __forceinline__ void fmarow2p(V32& h0, V32& h1, ull v0, ull v1,
                                         const float* __restrict__ wr) {
#pragma unroll
    for (int j = 0; j < 8; j++) {
        ulonglong2 w = *(const ulonglong2*)(wr + j * 4);
        ffma2(h0.u[2 * j + 0], v0, w.x);
        ffma2(h0.u[2 * j + 1], v0, w.y);
        ffma2(h1.u[2 * j + 0], v1, w.x);
        ffma2(h1.u[2 * j + 1], v1, w.y);
    }
}
__device__ __forceinline__ void ldbias(V32& h, const float* __restrict__ b) {
#pragma unroll
    for (int j = 0; j < FF; j++) h.f[j] = b[j];
}
__device__ __forceinline__ void relu32(V32& h) {
#pragma unroll
    for (int j = 0; j < FF; j++) h.f[j] = fmaxf(h.f[j], 0.f);
}
__device__ __forceinline__ void store_relu32(float* __restrict__ dst, const V32& o) {
#pragma unroll
    for (int j = 0; j < FF; j += 4) {
        *(float4*)(dst + j) = make_float4(fmaxf(o.f[j], 0.f), fmaxf(o.f[j + 1], 0.f),
                                          fmaxf(o.f[j + 2], 0.f), fmaxf(o.f[j + 3], 0.f));
    }
}
__device__ __forceinline__ void scatter32(float* __restrict__ acc, const V32& o) {
#pragma unroll
    for (int j = 0; j < FF; j += 4) red4(acc + j, o.f[j], o.f[j + 1], o.f[j + 2], o.f[j + 3]);
}
__device__ __forceinline__ void layer2p(V32& o0, V32& o1, const V32& h0, const V32& h1,
                                        const float* __restrict__ sw1,
                                        const float* __restrict__ sb1) {
    ldbias(o0, sb1);
    ldbias(o1, sb1);
#pragma unroll
    for (int k = 0; k < FF; k++) fmarow2p(o0, o1, pk2(h0.f[k]), pk2(h1.f[k]), sw1 + k * FF);
}

__global__ __launch_bounds__(128) void k_conv1(const float* __restrict__ ea,
                                               const int* __restrict__ eidx,
                                               const float* __restrict__ w10,
                                               const float* __restrict__ b10,
                                               const float* __restrict__ w11,
                                               const float* __restrict__ b11) {
    __shared__ __align__(16) float s_w0[4 * FF];
    __shared__ __align__(16) float s_b0[FF];
    __shared__ __align__(16) float s_w1[FF * FF];
    __shared__ __align__(16) float s_b1[FF];
    int tid = threadIdx.x, nt = blockDim.x;
    cpsh(s_w0, w10, 4 * FF, tid, nt);
    cpsh(s_b0, b10, FF, tid, nt);
    cpsh(s_w1, w11, FF * FF, tid, nt);
    cpsh(s_b1, b11, FF, tid, nt);
    __syncthreads();

    int p = blockIdx.x * nt + tid;
    if (p >= HALF_E) return;
    int e0 = 2 * p, e1 = 2 * p + 1;

    float4 a0 = *(const float4*)(ea + (size_t)e0 * 4);
    float4 a1 = *(const float4*)(ea + (size_t)e1 * 4);
    V32 h0, h1;
    ldbias(h0, s_b0);
    ldbias(h1, s_b0);
    fmarow2p(h0, h1, pk2(a0.x), pk2(a1.x), s_w0);
    fmarow2p(h0, h1, pk2(a0.y), pk2(a1.y), s_w0 + FF);
    fmarow2p(h0, h1, pk2(a0.z), pk2(a1.z), s_w0 + 2 * FF);
    fmarow2p(h0, h1, pk2(a0.w), pk2(a1.w), s_w0 + 3 * FF);
    relu32(h0);
    relu32(h1);

    V32 o0, o1;
    layer2p(o0, o1, h0, h1, s_w1, s_b1);

    int r0 = eidx[e0], r1 = eidx[e1];
    scatter32(g_acc1 + (size_t)r0 * FF, o0);
    scatter32(g_acc1 + (size_t)r1 * FF, o1);
    atomicAdd(&g_cnt[r0], 1.0f);
    atomicAdd(&g_cnt[r1], 1.0f);
    store_relu32(g_e1 + (size_t)e0 * FF, o0);
    store_relu32(g_e1 + (size_t)e1 * FF, o1);
}

// ---------------- conv2 tile: K=100 = [x1[r], x1[c], ea, e1] ----------------
// smem float offsets
#define C2_XS 0
#define C2_WS0 13200
#define C2_W1S 16400
#define C2_B0S 17424
#define C2_B1S 17456
#define C2_HS 17488
#define C2_ISR 21712
#define C2_ISC 21840
#define C2_TOT 21968

__global__ __launch_bounds__(TBT) void k_conv2t(const float* __restrict__ ea,
                                                const int* __restrict__ eidx,
                                                const float* __restrict__ w20,
                                                const float* __restrict__ b20,
                                                const float* __restrict__ w21,
                                                const float* __restrict__ b21) {
    extern __shared__ float sm[];
    float* Xs = sm + C2_XS;
    float* Ws0 = sm + C2_WS0;
    float* W1s = sm + C2_W1S;
    float* b0s = sm + C2_B0S;
    float* b1s = sm + C2_B1S;
    float* Hs = sm + C2_HS;
    int* Isr = (int*)(sm + C2_ISR);
    int* Isc = (int*)(sm + C2_ISC);

    int tid = threadIdx.x;
    int base = blockIdx.x * EPT;

    if (tid < EPT) {
        Isr[tid] = eidx[base + tid];
        Isc[tid] = eidx[EE + base + tid];
    }
    cpsh(Ws0, w20, 100 * FF, tid, TBT);
    cpsh(W1s, w21, FF * FF, tid, TBT);
    cpsh(b0s, b20, FF, tid, TBT);
    cpsh(b1s, b21, FF, tid, TBT);
    __syncthreads();

    stage32(Xs, 0, g_acc1, Isr, base, tid);
    stage32(Xs, 32, g_acc1, Isc, base, tid);
    stage4(Xs, 64, ea, base, tid);
    stage32(Xs, 68, g_e1, nullptr, base, tid);
    __syncthreads();

    int eg = tid >> 3, cg = tid & 7;
    ull acc[8];
    gemm_acc<100>(Xs, Ws0, b0s, eg, cg, acc);
    store_kmajor(Hs, acc, eg, cg, true);
    __syncthreads();
    gemm_acc<32>(Hs, W1s, b1s, eg, cg, acc);

#pragma unroll
    for (int e = 0; e < 4; e++) {
        U2 a, b;
        a.u = acc[2 * e];
        b.u = acc[2 * e + 1];
        int le = eg * 4 + e;
        int r = Isr[le];
        red4(g_acc2 + (size_t)r * FF + cg * 4, a.f[0], a.f[1], b.f[0], b.f[1]);
        *(float4*)(g_e2 + (size_t)(base + le) * FF + cg * 4) =
            make_float4(fmaxf(a.f[0], 0.f), fmaxf(a.f[1], 0.f), fmaxf(b.f[0], 0.f),
                        fmaxf(b.f[1], 0.f));
    }
}

// ---------------- conv3 tile: K=192 = [x2[r], x1[r], x2[c], x1[c], e2, e1] ----------------
#define C3_XS 0
#define C3_WS0 25344
#define C3_W1S 31488
#define C3_B0S 32512
#define C3_B1S 32544
#define C3_HS 32576
#define C3_ISR 36800
#define C3_ISC 36928
#define C3_TOT 37056

__global__ __launch_bounds__(TBT) void k_conv3t(const int* __restrict__ eidx,
                                                const float* __restrict__ w30,
                                                const float* __restrict__ b30,
                                                const float* __restrict__ w31,
                                                const float* __restrict__ b31) {
    extern __shared__ float sm[];
    float* Xs = sm + C3_XS;
    float* Ws0 = sm + C3_WS0;
    float* W1s = sm + C3_W1S;
    float* b0s = sm + C3_B0S;
    float* b1s = sm + C3_B1S;
    float* Hs = sm + C3_HS;
    int* Isr = (int*)(sm + C3_ISR);
    int* Isc = (int*)(sm + C3_ISC);

    int tid = threadIdx.x;
    int base = blockIdx.x * EPT;

    if (tid < EPT) {
        Isr[tid] = eidx[base + tid];
        Isc[tid] = eidx[EE + base + tid];
    }
    cpsh(Ws0, w30, 192 * FF, tid, TBT);
    cpsh(W1s, w31, FF * FF, tid, TBT);
    cpsh(b0s, b30, FF, tid, TBT);
    cpsh(b1s, b31, FF, tid, TBT);
    __syncthreads();

    stage32(Xs, 0, g_acc2, Isr, base, tid);
    stage32(Xs, 32, g_acc1, Isr, base, tid);
    stage32(Xs, 64, g_acc2, Isc, base, tid);
    stage32(Xs, 96, g_acc1, Isc, base, tid);
    stage32(Xs, 128, g_e2, nullptr, base, tid);
    stage32(Xs, 160, g_e1, nullptr, base, tid);
    __syncthreads();

    int eg = tid >> 3, cg = tid & 7;
    ull acc[8];
    gemm_acc<192>(Xs, Ws0, b0s, eg, cg, acc);
    store_kmajor(Hs, acc, eg, cg, true);
    __syncthreads();
    gemm_acc<32>(Hs, W1s, b1s, eg, cg, acc);

#pragma unroll
    for (int e = 0; e < 4; e++) {
        U2 a, b;
        a.u = acc[2 * e];
        b.u = acc[2 * e + 1];
        int le = eg * 4 + e;
        int r = Isr[le];
        red4(g_acc3 + (size_t)r * FF + cg * 4, a.f[0], a.f[1], b.f[0], b.f[1]);
        *(float4*)(g_e3 + (size_t)(base + le) * FF + cg * 4) =
            make_float4(fmaxf(a.f[0], 0.f), fmaxf(a.f[1], 0.f), fmaxf(b.f[0], 0.f),
                        fmaxf(b.f[1], 0.f));
    }
}

// ---------------- conv4 tile + heads ----------------
#define C4_XS 0
#define C4_WS0 25344
#define C4_W1S 31488
#define C4_W01S 32512
#define C4_W02S 33536
#define C4_WL1S 34560
#define C4_WL2S 34688
#define C4_B0S 34720
#define C4_B1S 34752
#define C4_B01S 34784
#define C4_B02S 34816
#define C4_BL1S 34848
#define C4_BL2S 34852
#define C4_HS 34856
#define C4_ISR 39080
#define C4_ISC 39208
#define C4_TOT 39336
// reuse of Xs region after layer 1:
#define C4_E4S C4_XS
#define C4_O01S (C4_XS + 4224)
#define C4_O02S (C4_XS + 8448)

__global__ __launch_bounds__(TBT) void k_conv4t(
    const float* __restrict__ ea, const int* __restrict__ eidx,
    const float* __restrict__ w40, const float* __restrict__ b40,
    const float* __restrict__ w41, const float* __restrict__ b41,
    const float* __restrict__ wl01, const float* __restrict__ bl01,
    const float* __restrict__ wl02, const float* __restrict__ bl02,
    const float* __restrict__ wl1, const float* __restrict__ bl1,
    const float* __restrict__ wl2, const float* __restrict__ bl2, float* __restrict__ out) {
    extern __shared__ float sm[];
    float* Xs = sm + C4_XS;
    float* Ws0 = sm + C4_WS0;
    float* W1s = sm + C4_W1S;
    float* W01s = sm + C4_W01S;
    float* W02s = sm + C4_W02S;
    float* wl1s = sm + C4_WL1S;
    float* wl2s = sm + C4_WL2S;
    float* b0s = sm + C4_B0S;
    float* b1s = sm + C4_B1S;
    float* b01s = sm + C4_B01S;
    float* b02s = sm + C4_B02S;
    float* bl1s = sm + C4_BL1S;
    float* bl2s = sm + C4_BL2S;
    float* Hs = sm + C4_HS;
    int* Isr = (int*)(sm + C4_ISR);
    int* Isc = (int*)(sm + C4_ISC);
    float* E4s = sm + C4_E4S;
    float* O01s = sm + C4_O01S;
    float* O02s = sm + C4_O02S;

    int tid = threadIdx.x;
    int base = blockIdx.x * EPT;

    if (tid < EPT) {
        Isr[tid] = eidx[base + tid];
        Isc[tid] = eidx[EE + base + tid];
    }
    cpsh(Ws0, w40, 192 * FF, tid, TBT);
    cpsh(W1s, w41, FF * FF, tid, TBT);
    cpsh(W01s, wl01, FF * FF, tid, TBT);
    cpsh(W02s, wl02, FF * FF, tid, TBT);
    cpsh(wl1s, wl1, FF * 4, tid, TBT);
    cpsh(wl2s, wl2, FF, tid, TBT);
    cpsh(b0s, b40, FF, tid, TBT);
    cpsh(b1s, b41, FF, tid, TBT);
    cpsh(b01s, bl01, FF, tid, TBT);
    cpsh(b02s, bl02, FF, tid, TBT);
    if (tid < 4) bl1s[tid] = bl1[tid];
    if (tid == 0) bl2s[0] = bl2[0];
    __syncthreads();

    stage32(Xs, 0, g_acc3, Isr, base, tid);
    stage32(Xs, 32, g_acc2, Isr, base, tid);
    stage32(Xs, 64, g_acc3, Isc, base, tid);
    stage32(Xs, 96, g_acc2, Isc, base, tid);
    stage32(Xs, 128, g_e3, nullptr, base, tid);
    stage32(Xs, 160, g_e2, nullptr, base, tid);
    __syncthreads();

    int eg = tid >> 3, cg = tid & 7;
    ull acc[8];
    gemm_acc<192>(Xs, Ws0, b0s, eg, cg, acc);
    store_kmajor(Hs, acc, eg, cg, true);
    __syncthreads();

    gemm_acc<32>(Hs, W1s, b1s, eg, cg, acc);  // e4 pre-relu
    store_kmajor(E4s, acc, eg, cg, true);     // relu(e4) -> E4s (Xs region, layer1 done)
    __syncthreads();

    gemm_acc<32>(E4s, W01s, b01s, eg, cg, acc);
    store_kmajor(O01s, acc, eg, cg, false);
    gemm_acc<32>(E4s, W02s, b02s, eg, cg, acc);
    store_kmajor(O02s, acc, eg, cg, false);
    __syncthreads();

    // per-edge heads
    if (tid < EPT) {
        int e = tid;
        int edge = base + e;
        float4 a = *(const float4*)(ea + (size_t)edge * 4);
        float ex0 = bl1s[0] + a.x, ex1 = bl1s[1] + a.y;
        float ex2 = bl1s[2] + a.z, ex3 = bl1s[3] + a.w;
#pragma unroll
        for (int k = 0; k < FF; k++) {
            float hv = O01s[(size_t)k * EPAD + e];
            ex0 += hv * wl1s[k * 4 + 0];
            ex1 += hv * wl1s[k * 4 + 1];
            ex2 += hv * wl1s[k * 4 + 2];
            ex3 += hv * wl1s[k * 4 + 3];
        }
        float nrm = sqrtf(ex0 * ex0 + ex1 * ex1 + ex2 * ex2 + ex3 * ex3);
        float inv = 1.0f / fmaxf(nrm, 1e-12f);
        *(float4*)(out + (size_t)EE + (size_t)edge * 4) =
            make_float4(ex0 * inv, ex1 * inv, ex2 * inv, ex3 * inv);

        float z = bl2s[0];
#pragma unroll
        for (int k = 0; k < FF; k++) z += O02s[(size_t)k * EPAD + e] * wl2s[k];
        out[edge] = 1.0f / (1.0f + expf(-z));
    }
}

// ---------------- launch ----------------
extern "C" void kernel_launch(void* const* d_in, const int* in_sizes, int n_in,
                              void* d_out, int out_size) {
    const int* eidx = (const int*)d_in[1];
    const float* ea = (const float*)d_in[2];
    const float* beta = (const float*)d_in[3];
    const float* w10 = (const float*)d_in[4];
    const float* b10 = (const float*)d_in[5];
    const float* w11 = (const float*)d_in[6];
    const float* b11 = (const float*)d_in[7];
    const float* w20 = (const float*)d_in[8];
    const float* b20 = (const float*)d_in[9];
    const float* w21 = (const float*)d_in[10];
    const float* b21 = (const float*)d_in[11];
    const float* w30 = (const float*)d_in[12];
    const float* b30 = (const float*)d_in[13];
    const float* w31 = (const float*)d_in[14];
    const float* b31 = (const float*)d_in[15];
    const float* w40 = (const float*)d_in[16];
    const float* b40 = (const float*)d_in[17];
    const float* w41 = (const float*)d_in[18];
    const float* b41 = (const float*)d_in[19];
    const float* wl01 = (const float*)d_in[20];
    const float* bl01 = (const float*)d_in[21];
    const float* wl02 = (const float*)d_in[22];
    const float* bl02 = (const float*)d_in[23];
    const float* wl1 = (const float*)d_in[24];
    const float* bl1 = (const float*)d_in[25];
    const float* wl2 = (const float*)d_in[26];
    const float* bl2 = (const float*)d_in[27];
    float* out = (float*)d_out;

    static int attr_done = 0;
    if (!attr_done) {
        cudaFuncSetAttribute(k_conv2t, cudaFuncAttributeMaxDynamicSharedMemorySize,
                             C2_TOT * 4);
        cudaFuncSetAttribute(k_conv3t, cudaFuncAttributeMaxDynamicSharedMemorySize,
                             C3_TOT * 4);
        cudaFuncSetAttribute(k_conv4t, cudaFuncAttributeMaxDynamicSharedMemorySize,
                             C4_TOT * 4);
        attr_done = 1;
    }

    const int T = 256;
    const int gridNF = (NN * FF + T - 1) / T;
    const int TB = 128;
    const int gridP = (HALF_E + TB - 1) / TB;

    k_init<<<gridNF, T>>>(beta, out);
    k_conv1<<<gridP, TB>>>(ea, eidx, w10, b10, w11, b11);
    k_final<<<gridNF, T>>>(0);
    k_conv2t<<<NTILES, TBT, C2_TOT * 4>>>(ea, eidx, w20, b20, w21, b21);
    k_final<<<gridNF, T>>>(1);
    k_conv3t<<<NTILES, TBT, C3_TOT * 4>>>(eidx, w30, b30, w31, b31);
    k_final<<<gridNF, T>>>(2);
    k_conv4t<<<NTILES, TBT, C4_TOT * 4>>>(ea, eidx, w40, b40, w41, b41, wl01, bl01, wl02,
                                          bl02, wl1, bl1, wl2, bl2, out);
}

// round 7
// speedup vs baseline: 2.0579x; 2.0579x over previous
#include <cuda_runtime.h>
#include <math.h>

#define NN 50000
#define EE 400000
#define FF 32
#define HALF_E (EE / 2)

typedef unsigned long long ull;

// ---------------- scratch (static device arrays; allocation-free) ----------------
__device__ __align__(128) float g_e1[(size_t)EE * FF];
__device__ __align__(128) float g_e2[(size_t)EE * FF];
__device__ __align__(128) float g_e3[(size_t)EE * FF];
__device__ __align__(128) float g_acc1[(size_t)NN * FF];
__device__ __align__(128) float g_acc2[(size_t)NN * FF];
__device__ __align__(128) float g_acc3[(size_t)NN * FF];
__device__ __align__(128) float g_uv[(size_t)NN * 64];  // per-conv node projections [U|V]
__device__ __align__(128) float g_cnt[NN];

// ---------------- f32x2 helpers ----------------
__device__ __forceinline__ void ffma2(ull& d, ull a, ull b) {
    asm("fma.rn.f32x2 %0, %1, %2, %0;" : "+l"(d) : "l"(a), "l"(b));
}
__device__ __forceinline__ ull pk2(float v) {
    ull r;
    asm("mov.b64 %0, {%1, %1};" : "=l"(r) : "f"(v));
    return r;
}
union V32 {
    float f[FF];
    ull u[FF / 2];
};

__device__ __forceinline__ void cpsh(float* dst, const float* src, int n, int tid, int nt) {
    for (int i = tid; i < n; i += nt) dst[i] = src[i];
}
__device__ __forceinline__ void ldbias(V32& h, const float* __restrict__ b) {
#pragma unroll
    for (int j = 0; j < FF; j++) h.f[j] = b[j];
}
__device__ __forceinline__ void relu32(V32& h) {
#pragma unroll
    for (int j = 0; j < FF; j++) h.f[j] = fmaxf(h.f[j], 0.f);
}
__device__ __forceinline__ void red4(float* __restrict__ a, float x, float y, float z, float w) {
    asm volatile("red.global.add.v4.f32 [%0], {%1, %2, %3, %4};" ::"l"(a), "f"(x), "f"(y),
                 "f"(z), "f"(w)
                 : "memory");
}
__device__ __forceinline__ void scatter32(float* __restrict__ acc, const V32& o) {
#pragma unroll
    for (int j = 0; j < FF; j += 4) red4(acc + j, o.f[j], o.f[j + 1], o.f[j + 2], o.f[j + 3]);
}
__device__ __forceinline__ void store_relu32(float* __restrict__ dst, const V32& o) {
#pragma unroll
    for (int j = 0; j < FF; j += 4) {
        *(float4*)(dst + j) = make_float4(fmaxf(o.f[j], 0.f), fmaxf(o.f[j + 1], 0.f),
                                          fmaxf(o.f[j + 2], 0.f), fmaxf(o.f[j + 3], 0.f));
    }
}

// single accumulator row: h += v * w_row
__device__ __forceinline__ void fmarow1(V32& h, ull v, const float* __restrict__ wr) {
#pragma unroll
    for (int j = 0; j < 8; j++) {
        ulonglong2 w = *(const ulonglong2*)(wr + j * 4);
        ffma2(h.u[2 * j + 0], v, w.x);
        ffma2(h.u[2 * j + 1], v, w.y);
    }
}
// pair: 2 edges share each weight load
__device__ __forceinline__ void fmarow2p(V32& h0, V32& h1, ull v0, ull v1,
                                         const float* __restrict__ wr) {
#pragma unroll
    for (int j = 0; j < 8; j++) {
        ulonglong2 w = *(const ulonglong2*)(wr + j * 4);
        ffma2(h0.u[2 * j + 0], v0, w.x);
        ffma2(h0.u[2 * j + 1], v0, w.y);
        ffma2(h1.u[2 * j + 0], v1, w.x);
        ffma2(h1.u[2 * j + 1], v1, w.y);
    }
}
__device__ __forceinline__ void seg32p(V32& h0, V32& h1, const float* __restrict__ s0,
                                       const float* __restrict__ s1,
                                       const float* __restrict__ ws) {
#pragma unroll
    for (int k = 0; k < FF; k += 4) {
        float4 a = *(const float4*)(s0 + k);
        float4 b = *(const float4*)(s1 + k);
        fmarow2p(h0, h1, pk2(a.x), pk2(b.x), ws + (k + 0) * FF);
        fmarow2p(h0, h1, pk2(a.y), pk2(b.y), ws + (k + 1) * FF);
        fmarow2p(h0, h1, pk2(a.z), pk2(b.z), ws + (k + 2) * FF);
        fmarow2p(h0, h1, pk2(a.w), pk2(b.w), ws + (k + 3) * FF);
    }
}
__device__ __forceinline__ void layer2p(V32& o0, V32& o1, const V32& h0, const V32& h1,
                                        const float* __restrict__ sw1,
                                        const float* __restrict__ sb1) {
    ldbias(o0, sb1);
    ldbias(o1, sb1);
#pragma unroll
    for (int k = 0; k < FF; k++) fmarow2p(o0, o1, pk2(h0.f[k]), pk2(h1.f[k]), sw1 + k * FF);
}

// h = U[r] + V[c]  (UV table: [N][64], U cols 0..31 with bias folded, V cols 32..63)
__device__ __forceinline__ void uvinit(V32& h, int r, int c) {
    const float* U = g_uv + (size_t)r * 64;
    const float* V = g_uv + (size_t)c * 64 + 32;
#pragma unroll
    for (int j = 0; j < FF; j += 4) {
        float4 a = *(const float4*)(U + j);
        float4 b = *(const float4*)(V + j);
        h.f[j + 0] = a.x + b.x;
        h.f[j + 1] = a.y + b.y;
        h.f[j + 2] = a.z + b.z;
        h.f[j + 3] = a.w + b.w;
    }
}

// ---------------- init / finalize ----------------
__global__ void k_init(const float* __restrict__ beta, float* __restrict__ out) {
    int i = blockIdx.x * blockDim.x + threadIdx.x;
    if (i < NN * FF) {
        g_acc1[i] = 0.f;
        g_acc2[i] = 0.f;
        g_acc3[i] = 0.f;
    }
    if (i < NN) g_cnt[i] = 0.f;
    if (i < 3 * NN) out[(size_t)5 * EE + i] = beta[i];
}
__global__ void k_final(int which) {
    int i = blockIdx.x * blockDim.x + threadIdx.x;
    if (i >= NN * FF) return;
    float* acc = (which == 0) ? g_acc1 : (which == 1) ? g_acc2 : g_acc3;
    float c = fmaxf(g_cnt[i >> 5], 1.0f);
    acc[i] = fmaxf(acc[i] / c, 0.0f);
}

// ---------------- node projection: uv[n] = [ xcat@W0r + b0 | xcat@W0c ] ----------------
// KP = rows per part per input half (32: single input xa; 64: concat [xa, xb])
template <int KP>
__global__ __launch_bounds__(128) void k_node(const float* __restrict__ xa,
                                              const float* __restrict__ xb,
                                              const float* __restrict__ W0,
                                              const float* __restrict__ b0) {
    __shared__ __align__(16) float s_w[2 * KP * FF];
    __shared__ __align__(16) float s_b[FF];
    int tid = threadIdx.x, nt = blockDim.x;
    cpsh(s_w, W0, 2 * KP * FF, tid, nt);
    cpsh(s_b, b0, FF, tid, nt);
    __syncthreads();

    int n = blockIdx.x * nt + tid;
    if (n >= NN) return;

    V32 u, v;
    ldbias(u, s_b);
#pragma unroll
    for (int j = 0; j < FF; j++) v.f[j] = 0.f;

    const float* xpa = xa + (size_t)n * FF;
#pragma unroll
    for (int k4 = 0; k4 < 8; k4++) {
        float4 xv = *(const float4*)(xpa + k4 * 4);
        int k = k4 * 4;
        fmarow1(u, pk2(xv.x), s_w + (k + 0) * FF);
        fmarow1(v, pk2(xv.x), s_w + (KP + k + 0) * FF);
        fmarow1(u, pk2(xv.y), s_w + (k + 1) * FF);
        fmarow1(v, pk2(xv.y), s_w + (KP + k + 1) * FF);
        fmarow1(u, pk2(xv.z), s_w + (k + 2) * FF);
        fmarow1(v, pk2(xv.z), s_w + (KP + k + 2) * FF);
        fmarow1(u, pk2(xv.w), s_w + (k + 3) * FF);
        fmarow1(v, pk2(xv.w), s_w + (KP + k + 3) * FF);
    }
    if (KP == 64) {
        const float* xpb = xb + (size_t)n * FF;
#pragma unroll
        for (int k4 = 0; k4 < 8; k4++) {
            float4 xv = *(const float4*)(xpb + k4 * 4);
            int k = 32 + k4 * 4;
            fmarow1(u, pk2(xv.x), s_w + (k + 0) * FF);
            fmarow1(v, pk2(xv.x), s_w + (KP + k + 0) * FF);
            fmarow1(u, pk2(xv.y), s_w + (k + 1) * FF);
            fmarow1(v, pk2(xv.y), s_w + (KP + k + 1) * FF);
            fmarow1(u, pk2(xv.z), s_w + (k + 2) * FF);
            fmarow1(v, pk2(xv.z), s_w + (KP + k + 2) * FF);
            fmarow1(u, pk2(xv.w), s_w + (k + 3) * FF);
            fmarow1(v, pk2(xv.w), s_w + (KP + k + 3) * FF);
        }
    }

    float* up = g_uv + (size_t)n * 64;
#pragma unroll
    for (int j = 0; j < FF; j += 4) *(float4*)(up + j) = *(float4*)(u.f + j);
#pragma unroll
    for (int j = 0; j < FF; j += 4) *(float4*)(up + 32 + j) = *(float4*)(v.f + j);
}

// ---------------- conv1 (pair, unchanged) ----------------
__global__ __launch_bounds__(128) void k_conv1(const float* __restrict__ ea,
                                               const int* __restrict__ eidx,
                                               const float* __restrict__ w10,
                                               const float* __restrict__ b10,
                                               const float* __restrict__ w11,
                                               const float* __restrict__ b11) {
    __shared__ __align__(16) float s_w0[4 * FF];
    __shared__ __align__(16) float s_b0[FF];
    __shared__ __align__(16) float s_w1[FF * FF];
    __shared__ __align__(16) float s_b1[FF];
    int tid = threadIdx.x, nt = blockDim.x;
    cpsh(s_w0, w10, 4 * FF, tid, nt);
    cpsh(s_b0, b10, FF, tid, nt);
    cpsh(s_w1, w11, FF * FF, tid, nt);
    cpsh(s_b1, b11, FF, tid, nt);
    __syncthreads();

    int p = blockIdx.x * nt + tid;
    if (p >= HALF_E) return;
    int e0 = 2 * p, e1 = 2 * p + 1;

    float4 a0 = *(const float4*)(ea + (size_t)e0 * 4);
    float4 a1 = *(const float4*)(ea + (size_t)e1 * 4);
    V32 h0, h1;
    ldbias(h0, s_b0);
    ldbias(h1, s_b0);
    fmarow2p(h0, h1, pk2(a0.x), pk2(a1.x), s_w0);
    fmarow2p(h0, h1, pk2(a0.y), pk2(a1.y), s_w0 + FF);
    fmarow2p(h0, h1, pk2(a0.z), pk2(a1.z), s_w0 + 2 * FF);
    fmarow2p(h0, h1, pk2(a0.w), pk2(a1.w), s_w0 + 3 * FF);
    relu32(h0);
    relu32(h1);

    V32 o0, o1;
    layer2p(o0, o1, h0, h1, s_w1, s_b1);

    int r0 = eidx[e0], r1 = eidx[e1];
    scatter32(g_acc1 + (size_t)r0 * FF, o0);
    scatter32(g_acc1 + (size_t)r1 * FF, o1);
    atomicAdd(&g_cnt[r0], 1.0f);
    atomicAdd(&g_cnt[r1], 1.0f);
    store_relu32(g_e1 + (size_t)e0 * FF, o0);
    store_relu32(g_e1 + (size_t)e1 * FF, o1);
}

// ---------------- edge2: h = UV2 + [ea, e1] @ w20[64:100] ----------------
__global__ __launch_bounds__(128) void k_edge2(const float* __restrict__ ea,
                                               const int* __restrict__ eidx,
                                               const float* __restrict__ w20,
                                               const float* __restrict__ w21,
                                               const float* __restrict__ b21) {
    __shared__ __align__(16) float s_w0e[36 * FF];
    __shared__ __align__(16) float s_w1[FF * FF];
    __shared__ __align__(16) float s_b1[FF];
    int tid = threadIdx.x, nt = blockDim.x;
    cpsh(s_w0e, w20 + 64 * FF, 36 * FF, tid, nt);
    cpsh(s_w1, w21, FF * FF, tid, nt);
    cpsh(s_b1, b21, FF, tid, nt);
    __syncthreads();

    int p = blockIdx.x * nt + tid;
    if (p >= HALF_E) return;
    int e0 = 2 * p, e1 = 2 * p + 1;
    int r0 = eidx[e0], c0 = eidx[EE + e0];
    int r1 = eidx[e1], c1 = eidx[EE + e1];

    V32 h0, h1;
    uvinit(h0, r0, c0);
    uvinit(h1, r1, c1);

    float4 a0 = *(const float4*)(ea + (size_t)e0 * 4);
    float4 a1 = *(const float4*)(ea + (size_t)e1 * 4);
    fmarow2p(h0, h1, pk2(a0.x), pk2(a1.x), s_w0e);
    fmarow2p(h0, h1, pk2(a0.y), pk2(a1.y), s_w0e + FF);
    fmarow2p(h0, h1, pk2(a0.z), pk2(a1.z), s_w0e + 2 * FF);
    fmarow2p(h0, h1, pk2(a0.w), pk2(a1.w), s_w0e + 3 * FF);
    seg32p(h0, h1, g_e1 + (size_t)e0 * FF, g_e1 + (size_t)e1 * FF, s_w0e + 4 * FF);
    relu32(h0);
    relu32(h1);

    V32 o0, o1;
    layer2p(o0, o1, h0, h1, s_w1, s_b1);

    scatter32(g_acc2 + (size_t)r0 * FF, o0);
    scatter32(g_acc2 + (size_t)r1 * FF, o1);
    store_relu32(g_e2 + (size_t)e0 * FF, o0);
    store_relu32(g_e2 + (size_t)e1 * FF, o1);
}

// ---------------- edge3: h = UV3 + [e2, e1] @ w30[128:192] ----------------
__global__ __launch_bounds__(128) void k_edge3(const int* __restrict__ eidx,
                                               const float* __restrict__ w30,
                                               const float* __restrict__ w31,
                                               const float* __restrict__ b31) {
    __shared__ __align__(16) float s_w0e[64 * FF];
    __shared__ __align__(16) float s_w1[FF * FF];
    __shared__ __align__(16) float s_b1[FF];
    int tid = threadIdx.x, nt = blockDim.x;
    cpsh(s_w0e, w30 + 128 * FF, 64 * FF, tid, nt);
    cpsh(s_w1, w31, FF * FF, tid, nt);
    cpsh(s_b1, b31, FF, tid, nt);
    __syncthreads();

    int p = blockIdx.x * nt + tid;
    if (p >= HALF_E) return;
    int e0 = 2 * p, e1 = 2 * p + 1;
    int r0 = eidx[e0], c0 = eidx[EE + e0];
    int r1 = eidx[e1], c1 = eidx[EE + e1];

    V32 h0, h1;
    uvinit(h0, r0, c0);
    uvinit(h1, r1, c1);
    seg32p(h0, h1, g_e2 + (size_t)e0 * FF, g_e2 + (size_t)e1 * FF, s_w0e);
    seg32p(h0, h1, g_e1 + (size_t)e0 * FF, g_e1 + (size_t)e1 * FF, s_w0e + 32 * FF);
    relu32(h0);
    relu32(h1);

    V32 o0, o1;
    layer2p(o0, o1, h0, h1, s_w1, s_b1);

    scatter32(g_acc3 + (size_t)r0 * FF, o0);
    scatter32(g_acc3 + (size_t)r1 * FF, o1);
    store_relu32(g_e3 + (size_t)e0 * FF, o0);
    store_relu32(g_e3 + (size_t)e1 * FF, o1);
}

// ---------------- edge4 + heads: h = UV4 + [e3, e2] @ w40[128:192] ----------------
__global__ __launch_bounds__(128) void k_edge4(
    const float* __restrict__ ea, const int* __restrict__ eidx,
    const float* __restrict__ w40, const float* __restrict__ w41,
    const float* __restrict__ b41, const float* __restrict__ wl01,
    const float* __restrict__ bl01, const float* __restrict__ wl02,
    const float* __restrict__ bl02, const float* __restrict__ wl1,
    const float* __restrict__ bl1, const float* __restrict__ wl2,
    const float* __restrict__ bl2, float* __restrict__ out) {
    __shared__ __align__(16) float s_w0e[64 * FF];
    __shared__ __align__(16) float s_w1[FF * FF];
    __shared__ __align__(16) float s_b1[FF];
    __shared__ __align__(16) float s_w01[FF * FF];
    __shared__ __align__(16) float s_b01[FF];
    __shared__ __align__(16) float s_w02[FF * FF];
    __shared__ __align__(16) float s_b02[FF];
    __shared__ __align__(16) float s_wl1[FF * 4];
    __shared__ __align__(16) float s_wl2[FF];
    __shared__ float s_bl1[4];
    __shared__ float s_bl2;
    int tid = threadIdx.x, nt = blockDim.x;
    cpsh(s_w0e, w40 + 128 * FF, 64 * FF, tid, nt);
    cpsh(s_w1, w41, FF * FF, tid, nt);
    cpsh(s_b1, b41, FF, tid, nt);
    cpsh(s_w01, wl01, FF * FF, tid, nt);
    cpsh(s_b01, bl01, FF, tid, nt);
    cpsh(s_w02, wl02, FF * FF, tid, nt);
    cpsh(s_b02, bl02, FF, tid, nt);
    cpsh(s_wl1, wl1, FF * 4, tid, nt);
    cpsh(s_wl2, wl2, FF, tid, nt);
    if (tid < 4) s_bl1[tid] = bl1[tid];
    if (tid == 0) s_bl2 = bl2[0];
    __syncthreads();

    int p = blockIdx.x * nt + tid;
    if (p >= HALF_E) return;
    int e0 = 2 * p, e1 = 2 * p + 1;
    int r0 = eidx[e0], c0 = eidx[EE + e0];
    int r1 = eidx[e1], c1 = eidx[EE + e1];

    V32 h0, h1;
    uvinit(h0, r0, c0);
    uvinit(h1, r1, c1);
    seg32p(h0, h1, g_e3 + (size_t)e0 * FF, g_e3 + (size_t)e1 * FF, s_w0e);
    seg32p(h0, h1, g_e2 + (size_t)e0 * FF, g_e2 + (size_t)e1 * FF, s_w0e + 32 * FF);
    relu32(h0);
    relu32(h1);

    V32 e40, e41;
    layer2p(e40, e41, h0, h1, s_w1, s_b1);
    relu32(e40);
    relu32(e41);

    // head 1
    layer2p(h0, h1, e40, e41, s_w01, s_b01);
#pragma unroll
    for (int side = 0; side < 2; side++) {
        const V32& hh = side ? h1 : h0;
        int e = side ? e1 : e0;
        float4 a = *(const float4*)(ea + (size_t)e * 4);
        float ex0 = s_bl1[0] + a.x, ex1 = s_bl1[1] + a.y;
        float ex2 = s_bl1[2] + a.z, ex3 = s_bl1[3] + a.w;
#pragma unroll
        for (int j = 0; j < FF; j++) {
            float4 w = *(const float4*)(s_wl1 + j * 4);
            ex0 += hh.f[j] * w.x;
            ex1 += hh.f[j] * w.y;
            ex2 += hh.f[j] * w.z;
            ex3 += hh.f[j] * w.w;
        }
        float nrm = sqrtf(ex0 * ex0 + ex1 * ex1 + ex2 * ex2 + ex3 * ex3);
        float inv = 1.0f / fmaxf(nrm, 1e-12f);
        *(float4*)(out + (size_t)EE + (size_t)e * 4) =
            make_float4(ex0 * inv, ex1 * inv, ex2 * inv, ex3 * inv);
    }

    // head 2
    layer2p(h0, h1, e40, e41, s_w02, s_b02);
#pragma unroll
    for (int side = 0; side < 2; side++) {
        const V32& hh = side ? h1 : h0;
        int e = side ? e1 : e0;
        float z = s_bl2;
#pragma unroll
        for (int j = 0; j < FF; j++) z += hh.f[j] * s_wl2[j];
        out[e] = 1.0f / (1.0f + expf(-z));
    }
}

// ---------------- launch ----------------
extern "C" void kernel_launch(void* const* d_in, const int* in_sizes, int n_in,
                              void* d_out, int out_size) {
    const int* eidx = (const int*)d_in[1];
    const float* ea = (const float*)d_in[2];
    const float* beta = (const float*)d_in[3];
    const float* w10 = (const float*)d_in[4];
    const float* b10 = (const float*)d_in[5];
    const float* w11 = (const float*)d_in[6];
    const float* b11 = (const float*)d_in[7];
    const float* w20 = (const float*)d_in[8];
    const float* b20 = (const float*)d_in[9];
    const float* w21 = (const float*)d_in[10];
    const float* b21 = (const float*)d_in[11];
    const float* w30 = (const float*)d_in[12];
    const float* b30 = (const float*)d_in[13];
    const float* w31 = (const float*)d_in[14];
    const float* b31 = (const float*)d_in[15];
    const float* w40 = (const float*)d_in[16];
    const float* b40 = (const float*)d_in[17];
    const float* w41 = (const float*)d_in[18];
    const float* b41 = (const float*)d_in[19];
    const float* wl01 = (const float*)d_in[20];
    const float* bl01 = (const float*)d_in[21];
    const float* wl02 = (const float*)d_in[22];
    const float* bl02 = (const float*)d_in[23];
    const float* wl1 = (const float*)d_in[24];
    const float* bl1 = (const float*)d_in[25];
    const float* wl2 = (const float*)d_in[26];
    const float* bl2 = (const float*)d_in[27];
    float* out = (float*)d_out;

    // resolve device scratch addresses (host-side; graph-capturable)
    float *acc1p, *acc2p, *acc3p;
    cudaGetSymbolAddress((void**)&acc1p, g_acc1);
    cudaGetSymbolAddress((void**)&acc2p, g_acc2);
    cudaGetSymbolAddress((void**)&acc3p, g_acc3);

    const int T = 256;
    const int gridNF = (NN * FF + T - 1) / T;
    const int TB = 128;
    const int gridP = (HALF_E + TB - 1) / TB;
    const int gridN = (NN + TB - 1) / TB;

    k_init<<<gridNF, T>>>(beta, out);
    k_conv1<<<gridP, TB>>>(ea, eidx, w10, b10, w11, b11);
    k_final<<<gridNF, T>>>(0);

    k_node<32><<<gridN, TB>>>(acc1p, nullptr, w20, b20);
    k_edge2<<<gridP, TB>>>(ea, eidx, w20, w21, b21);
    k_final<<<gridNF, T>>>(1);

    k_node<64><<<gridN, TB>>>(acc2p, acc1p, w30, b30);
    k_edge3<<<gridP, TB>>>(eidx, w30, w31, b31);
    k_final<<<gridNF, T>>>(2);

    k_node<64><<<gridN, TB>>>(acc3p, acc2p, w40, b40);
    k_edge4<<<gridP, TB>>>(ea, eidx, w40, w41, b41, wl01, bl01, wl02, bl02, wl1, bl1,
                           wl2, bl2, out);
}

// round 8
// speedup vs baseline: 2.3806x; 1.1568x over previous
#include <cuda_runtime.h>
#include <math.h>

#define NN 50000
#define EE 400000
#define FF 32
#define HALF_E (EE / 2)

typedef unsigned long long ull;

// ---------------- scratch ----------------
__device__ __align__(128) float g_e1[(size_t)EE * FF];
__device__ __align__(128) float g_e2[(size_t)EE * FF];
__device__ __align__(128) float g_e3[(size_t)EE * FF];
__device__ __align__(128) float g_acc1[(size_t)NN * FF];
__device__ __align__(128) float g_acc2[(size_t)NN * FF];
__device__ __align__(128) float g_acc3[(size_t)NN * FF];
__device__ __align__(128) float g_uv[(size_t)NN * 64];
__device__ __align__(128) float g_cnt[NN];
// folded head weights
__device__ __align__(16) float g_wx[FF * 4];
__device__ __align__(16) float g_bx[4];
__device__ __align__(16) float g_wz[FF];
__device__ float g_bz;

// ---------------- f32x2 helpers ----------------
__device__ __forceinline__ void ffma2(ull& d, ull a, ull b) {
    asm("fma.rn.f32x2 %0, %1, %2, %0;" : "+l"(d) : "l"(a), "l"(b));
}
__device__ __forceinline__ ull pk2(float v) {
    ull r;
    asm("mov.b64 %0, {%1, %1};" : "=l"(r) : "f"(v));
    return r;
}
union V32 {
    float f[FF];
    ull u[FF / 2];
};

__device__ __forceinline__ void cpsh(float* dst, const float* src, int n, int tid, int nt) {
    for (int i = tid; i < n; i += nt) dst[i] = src[i];
}
__device__ __forceinline__ void ldbias(V32& h, const float* __restrict__ b) {
#pragma unroll
    for (int j = 0; j < FF; j++) h.f[j] = b[j];
}
__device__ __forceinline__ void relu32(V32& h) {
#pragma unroll
    for (int j = 0; j < FF; j++) h.f[j] = fmaxf(h.f[j], 0.f);
}
__device__ __forceinline__ void red4(float* __restrict__ a, float x, float y, float z, float w) {
    asm volatile("red.global.add.v4.f32 [%0], {%1, %2, %3, %4};" ::"l"(a), "f"(x), "f"(y),
                 "f"(z), "f"(w)
                 : "memory");
}
__device__ __forceinline__ void scatter32(float* __restrict__ acc, const V32& o) {
#pragma unroll
    for (int j = 0; j < FF; j += 4) red4(acc + j, o.f[j], o.f[j + 1], o.f[j + 2], o.f[j + 3]);
}
__device__ __forceinline__ void store_relu32(float* __restrict__ dst, const V32& o) {
#pragma unroll
    for (int j = 0; j < FF; j += 4) {
        *(float4*)(dst + j) = make_float4(fmaxf(o.f[j], 0.f), fmaxf(o.f[j + 1], 0.f),
                                          fmaxf(o.f[j + 2], 0.f), fmaxf(o.f[j + 3], 0.f));
    }
}

__device__ __forceinline__ void fmarow1(V32& h, ull v, const float* __restrict__ wr) {
#pragma unroll
    for (int j = 0; j < 8; j++) {
        ulonglong2 w = *(const ulonglong2*)(wr + j * 4);
        ffma2(h.u[2 * j + 0], v, w.x);
        ffma2(h.u[2 * j + 1], v, w.y);
    }
}
__device__ __forceinline__ void fmarow2p(V32& h0, V32& h1, ull v0, ull v1,
                                         const float* __restrict__ wr) {
#pragma unroll
    for (int j = 0; j < 8; j++) {
        ulonglong2 w = *(const ulonglong2*)(wr + j * 4);
        ffma2(h0.u[2 * j + 0], v0, w.x);
        ffma2(h0.u[2 * j + 1], v0, w.y);
        ffma2(h1.u[2 * j + 0], v1, w.x);
        ffma2(h1.u[2 * j + 1], v1, w.y);
    }
}
__device__ __forceinline__ void seg32p(V32& h0, V32& h1, const float* __restrict__ s0,
                                       const float* __restrict__ s1,
                                       const float* __restrict__ ws) {
#pragma unroll
    for (int k = 0; k < FF; k += 4) {
        float4 a = *(const float4*)(s0 + k);
        float4 b = *(const float4*)(s1 + k);
        fmarow2p(h0, h1, pk2(a.x), pk2(b.x), ws + (k + 0) * FF);
        fmarow2p(h0, h1, pk2(a.y), pk2(b.y), ws + (k + 1) * FF);
        fmarow2p(h0, h1, pk2(a.z), pk2(b.z), ws + (k + 2) * FF);
        fmarow2p(h0, h1, pk2(a.w), pk2(b.w), ws + (k + 3) * FF);
    }
}
__device__ __forceinline__ void layer2p(V32& o0, V32& o1, const V32& h0, const V32& h1,
                                        const float* __restrict__ sw1,
                                        const float* __restrict__ sb1) {
    ldbias(o0, sb1);
    ldbias(o1, sb1);
#pragma unroll
    for (int k = 0; k < FF; k++) fmarow2p(o0, o1, pk2(h0.f[k]), pk2(h1.f[k]), sw1 + k * FF);
}
__device__ __forceinline__ void uvinit(V32& h, int r, int c) {
    const float* U = g_uv + (size_t)r * 64;
    const float* V = g_uv + (size_t)c * 64 + 32;
#pragma unroll
    for (int j = 0; j < FF; j += 4) {
        float4 a = *(const float4*)(U + j);
        float4 b = *(const float4*)(V + j);
        h.f[j + 0] = a.x + b.x;
        h.f[j + 1] = a.y + b.y;
        h.f[j + 2] = a.z + b.z;
        h.f[j + 3] = a.w + b.w;
    }
}

// ---------------- init ----------------
__global__ void k_init(const float* __restrict__ beta, float* __restrict__ out) {
    int i = blockIdx.x * blockDim.x + threadIdx.x;
    if (i < NN * FF) {
        g_acc1[i] = 0.f;
        g_acc2[i] = 0.f;
        g_acc3[i] = 0.f;
    }
    if (i < NN) g_cnt[i] = 0.f;
    if (i < 3 * NN) out[(size_t)5 * EE + i] = beta[i];
}

// ---------------- head fold: Wx = wl01@wl1, bx = bl01@wl1+bl1, wz = wl02@wl2, bz ----------------
__global__ void k_headfold(const float* __restrict__ wl01, const float* __restrict__ bl01,
                           const float* __restrict__ wl02, const float* __restrict__ bl02,
                           const float* __restrict__ wl1, const float* __restrict__ bl1,
                           const float* __restrict__ wl2, const float* __restrict__ bl2) {
    int t = threadIdx.x;
    if (t < 128) {  // Wx[k][j]
        int k = t >> 2, j = t & 3;
        float s = 0.f;
#pragma unroll
        for (int m = 0; m < FF; m++) s += wl01[k * FF + m] * wl1[m * 4 + j];
        g_wx[k * 4 + j] = s;
    }
    if (t < 4) {  // bx[j]
        float s = bl1[t];
#pragma unroll
        for (int m = 0; m < FF; m++) s += bl01[m] * wl1[m * 4 + t];
        g_bx[t] = s;
    }
    if (t >= 128 && t < 160) {  // wz[k]
        int k = t - 128;
        float s = 0.f;
#pragma unroll
        for (int m = 0; m < FF; m++) s += wl02[k * FF + m] * wl2[m];
        g_wz[k] = s;
    }
    if (t == 160) {  // bz
        float s = bl2[0];
#pragma unroll
        for (int m = 0; m < FF; m++) s += bl02[m] * wl2[m];
        g_bz = s;
    }
}

// ---------------- node projection with fused finalize ----------------
// block: 256 threads, 128 nodes; warps 0-3 = U (bias folded), warps 4-7 = V.
// input x = relu(acc/max(cnt,1)) computed on load.
template <int KP>
__global__ __launch_bounds__(256) void k_node(const float* __restrict__ acca,
                                              const float* __restrict__ accb,
                                              const float* __restrict__ W0,
                                              const float* __restrict__ b0) {
    __shared__ __align__(16) float s_w[2 * KP * FF];
    __shared__ __align__(16) float s_b[FF];
    int tid = threadIdx.x;
    cpsh(s_w, W0, 2 * KP * FF, tid, 256);
    cpsh(s_b, b0, FF, tid, 256);
    __syncthreads();

    int isV = tid >> 7;  // 0 = U, 1 = V
    int n = blockIdx.x * 128 + (tid & 127);
    if (n >= NN) return;

    float inv = 1.0f / fmaxf(g_cnt[n], 1.0f);
    const float* ws = s_w + (isV ? KP * FF : 0);

    V32 acc;
    if (isV) {
#pragma unroll
        for (int j = 0; j < FF; j++) acc.f[j] = 0.f;
    } else {
        ldbias(acc, s_b);
    }

    const float* xpa = acca + (size_t)n * FF;
#pragma unroll
    for (int k4 = 0; k4 < 8; k4++) {
        float4 xv = *(const float4*)(xpa + k4 * 4);
        xv.x = fmaxf(xv.x, 0.f) * inv;
        xv.y = fmaxf(xv.y, 0.f) * inv;
        xv.z = fmaxf(xv.z, 0.f) * inv;
        xv.w = fmaxf(xv.w, 0.f) * inv;
        int k = k4 * 4;
        fmarow1(acc, pk2(xv.x), ws + (k + 0) * FF);
        fmarow1(acc, pk2(xv.y), ws + (k + 1) * FF);
        fmarow1(acc, pk2(xv.z), ws + (k + 2) * FF);
        fmarow1(acc, pk2(xv.w), ws + (k + 3) * FF);
    }
    if (KP == 64) {
        const float* xpb = accb + (size_t)n * FF;
#pragma unroll
        for (int k4 = 0; k4 < 8; k4++) {
            float4 xv = *(const float4*)(xpb + k4 * 4);
            xv.x = fmaxf(xv.x, 0.f) * inv;
            xv.y = fmaxf(xv.y, 0.f) * inv;
            xv.z = fmaxf(xv.z, 0.f) * inv;
            xv.w = fmaxf(xv.w, 0.f) * inv;
            int k = 32 + k4 * 4;
            fmarow1(acc, pk2(xv.x), ws + (k + 0) * FF);
            fmarow1(acc, pk2(xv.y), ws + (k + 1) * FF);
            fmarow1(acc, pk2(xv.z), ws + (k + 2) * FF);
            fmarow1(acc, pk2(xv.w), ws + (k + 3) * FF);
        }
    }

    float* up = g_uv + (size_t)n * 64 + isV * 32;
#pragma unroll
    for (int j = 0; j < FF; j += 4) *(float4*)(up + j) = *(float4*)(acc.f + j);
}

// ---------------- conv1 (pair) ----------------
__global__ __launch_bounds__(128) void k_conv1(const float* __restrict__ ea,
                                               const int* __restrict__ eidx,
                                               const float* __restrict__ w10,
                                               const float* __restrict__ b10,
                                               const float* __restrict__ w11,
                                               const float* __restrict__ b11) {
    __shared__ __align__(16) float s_w0[4 * FF];
    __shared__ __align__(16) float s_b0[FF];
    __shared__ __align__(16) float s_w1[FF * FF];
    __shared__ __align__(16) float s_b1[FF];
    int tid = threadIdx.x, nt = blockDim.x;
    cpsh(s_w0, w10, 4 * FF, tid, nt);
    cpsh(s_b0, b10, FF, tid, nt);
    cpsh(s_w1, w11, FF * FF, tid, nt);
    cpsh(s_b1, b11, FF, tid, nt);
    __syncthreads();

    int p = blockIdx.x * nt + tid;
    if (p >= HALF_E) return;
    int e0 = 2 * p, e1 = 2 * p + 1;

    float4 a0 = *(const float4*)(ea + (size_t)e0 * 4);
    float4 a1 = *(const float4*)(ea + (size_t)e1 * 4);
    V32 h0, h1;
    ldbias(h0, s_b0);
    ldbias(h1, s_b0);
    fmarow2p(h0, h1, pk2(a0.x), pk2(a1.x), s_w0);
    fmarow2p(h0, h1, pk2(a0.y), pk2(a1.y), s_w0 + FF);
    fmarow2p(h0, h1, pk2(a0.z), pk2(a1.z), s_w0 + 2 * FF);
    fmarow2p(h0, h1, pk2(a0.w), pk2(a1.w), s_w0 + 3 * FF);
    relu32(h0);
    relu32(h1);

    V32 o0, o1;
    layer2p(o0, o1, h0, h1, s_w1, s_b1);

    int r0 = eidx[e0], r1 = eidx[e1];
    scatter32(g_acc1 + (size_t)r0 * FF, o0);
    scatter32(g_acc1 + (size_t)r1 * FF, o1);
    atomicAdd(&g_cnt[r0], 1.0f);
    atomicAdd(&g_cnt[r1], 1.0f);
    store_relu32(g_e1 + (size_t)e0 * FF, o0);
    store_relu32(g_e1 + (size_t)e1 * FF, o1);
}

// ---------------- edge2 ----------------
__global__ __launch_bounds__(128) void k_edge2(const float* __restrict__ ea,
                                               const int* __restrict__ eidx,
                                               const float* __restrict__ w20,
                                               const float* __restrict__ w21,
                                               const float* __restrict__ b21) {
    __shared__ __align__(16) float s_w0e[36 * FF];
    __shared__ __align__(16) float s_w1[FF * FF];
    __shared__ __align__(16) float s_b1[FF];
    int tid = threadIdx.x, nt = blockDim.x;
    cpsh(s_w0e, w20 + 64 * FF, 36 * FF, tid, nt);
    cpsh(s_w1, w21, FF * FF, tid, nt);
    cpsh(s_b1, b21, FF, tid, nt);
    __syncthreads();

    int p = blockIdx.x * nt + tid;
    if (p >= HALF_E) return;
    int e0 = 2 * p, e1 = 2 * p + 1;
    int r0 = eidx[e0], c0 = eidx[EE + e0];
    int r1 = eidx[e1], c1 = eidx[EE + e1];

    V32 h0, h1;
    uvinit(h0, r0, c0);
    uvinit(h1, r1, c1);

    float4 a0 = *(const float4*)(ea + (size_t)e0 * 4);
    float4 a1 = *(const float4*)(ea + (size_t)e1 * 4);
    fmarow2p(h0, h1, pk2(a0.x), pk2(a1.x), s_w0e);
    fmarow2p(h0, h1, pk2(a0.y), pk2(a1.y), s_w0e + FF);
    fmarow2p(h0, h1, pk2(a0.z), pk2(a1.z), s_w0e + 2 * FF);
    fmarow2p(h0, h1, pk2(a0.w), pk2(a1.w), s_w0e + 3 * FF);
    seg32p(h0, h1, g_e1 + (size_t)e0 * FF, g_e1 + (size_t)e1 * FF, s_w0e + 4 * FF);
    relu32(h0);
    relu32(h1);

    V32 o0, o1;
    layer2p(o0, o1, h0, h1, s_w1, s_b1);

    scatter32(g_acc2 + (size_t)r0 * FF, o0);
    scatter32(g_acc2 + (size_t)r1 * FF, o1);
    store_relu32(g_e2 + (size_t)e0 * FF, o0);
    store_relu32(g_e2 + (size_t)e1 * FF, o1);
}

// ---------------- edge3 ----------------
__global__ __launch_bounds__(128) void k_edge3(const int* __restrict__ eidx,
                                               const float* __restrict__ w30,
                                               const float* __restrict__ w31,
                                               const float* __restrict__ b31) {
    __shared__ __align__(16) float s_w0e[64 * FF];
    __shared__ __align__(16) float s_w1[FF * FF];
    __shared__ __align__(16) float s_b1[FF];
    int tid = threadIdx.x, nt = blockDim.x;
    cpsh(s_w0e, w30 + 128 * FF, 64 * FF, tid, nt);
    cpsh(s_w1, w31, FF * FF, tid, nt);
    cpsh(s_b1, b31, FF, tid, nt);
    __syncthreads();

    int p = blockIdx.x * nt + tid;
    if (p >= HALF_E) return;
    int e0 = 2 * p, e1 = 2 * p + 1;
    int r0 = eidx[e0], c0 = eidx[EE + e0];
    int r1 = eidx[e1], c1 = eidx[EE + e1];

    V32 h0, h1;
    uvinit(h0, r0, c0);
    uvinit(h1, r1, c1);
    seg32p(h0, h1, g_e2 + (size_t)e0 * FF, g_e2 + (size_t)e1 * FF, s_w0e);
    seg32p(h0, h1, g_e1 + (size_t)e0 * FF, g_e1 + (size_t)e1 * FF, s_w0e + 32 * FF);
    relu32(h0);
    relu32(h1);

    V32 o0, o1;
    layer2p(o0, o1, h0, h1, s_w1, s_b1);

    scatter32(g_acc3 + (size_t)r0 * FF, o0);
    scatter32(g_acc3 + (size_t)r1 * FF, o1);
    store_relu32(g_e3 + (size_t)e0 * FF, o0);
    store_relu32(g_e3 + (size_t)e1 * FF, o1);
}

// ---------------- edge4 + folded heads ----------------
__global__ __launch_bounds__(128) void k_edge4(const float* __restrict__ ea,
                                               const int* __restrict__ eidx,
                                               const float* __restrict__ w40,
                                               const float* __restrict__ w41,
                                               const float* __restrict__ b41,
                                               float* __restrict__ out) {
    __shared__ __align__(16) float s_w0e[64 * FF];
    __shared__ __align__(16) float s_w1[FF * FF];
    __shared__ __align__(16) float s_b1[FF];
    __shared__ __align__(16) float s_wx[FF * 4];
    __shared__ __align__(16) float s_wz[FF];
    __shared__ float s_bx[4];
    __shared__ float s_bz;
    int tid = threadIdx.x, nt = blockDim.x;
    cpsh(s_w0e, w40 + 128 * FF, 64 * FF, tid, nt);
    cpsh(s_w1, w41, FF * FF, tid, nt);
    cpsh(s_b1, b41, FF, tid, nt);
    cpsh(s_wx, g_wx, FF * 4, tid, nt);
    cpsh(s_wz, g_wz, FF, tid, nt);
    if (tid < 4) s_bx[tid] = g_bx[tid];
    if (tid == 0) s_bz = g_bz;
    __syncthreads();

    int p = blockIdx.x * nt + tid;
    if (p >= HALF_E) return;
    int e0 = 2 * p, e1 = 2 * p + 1;
    int r0 = eidx[e0], c0 = eidx[EE + e0];
    int r1 = eidx[e1], c1 = eidx[EE + e1];

    V32 h0, h1;
    uvinit(h0, r0, c0);
    uvinit(h1, r1, c1);
    seg32p(h0, h1, g_e3 + (size_t)e0 * FF, g_e3 + (size_t)e1 * FF, s_w0e);
    seg32p(h0, h1, g_e2 + (size_t)e0 * FF, g_e2 + (size_t)e1 * FF, s_w0e + 32 * FF);
    relu32(h0);
    relu32(h1);

    V32 e40, e41;
    layer2p(e40, e41, h0, h1, s_w1, s_b1);
    relu32(e40);
    relu32(e41);

    // folded heads: edge_x = e4 @ Wx + bx + ea ; z = e4 . wz + bz
    float4 a0 = *(const float4*)(ea + (size_t)e0 * 4);
    float4 a1 = *(const float4*)(ea + (size_t)e1 * 4);
    float x00 = s_bx[0] + a0.x, x01 = s_bx[1] + a0.y, x02 = s_bx[2] + a0.z,
          x03 = s_bx[3] + a0.w;
    float x10 = s_bx[0] + a1.x, x11 = s_bx[1] + a1.y, x12 = s_bx[2] + a1.z,
          x13 = s_bx[3] + a1.w;
    float z0 = s_bz, z1 = s_bz;
#pragma unroll
    for (int k = 0; k < FF; k++) {
        float4 w = *(const float4*)(s_wx + k * 4);
        float wzk = s_wz[k];
        float v0 = e40.f[k], v1 = e41.f[k];
        x00 += v0 * w.x;
        x01 += v0 * w.y;
        x02 += v0 * w.z;
        x03 += v0 * w.w;
        z0 += v0 * wzk;
        x10 += v1 * w.x;
        x11 += v1 * w.y;
        x12 += v1 * w.z;
        x13 += v1 * w.w;
        z1 += v1 * wzk;
    }
    {
        float nrm = sqrtf(x00 * x00 + x01 * x01 + x02 * x02 + x03 * x03);
        float inv = 1.0f / fmaxf(nrm, 1e-12f);
        *(float4*)(out + (size_t)EE + (size_t)e0 * 4) =
            make_float4(x00 * inv, x01 * inv, x02 * inv, x03 * inv);
    }
    {
        float nrm = sqrtf(x10 * x10 + x11 * x11 + x12 * x12 + x13 * x13);
        float inv = 1.0f / fmaxf(nrm, 1e-12f);
        *(float4*)(out + (size_t)EE + (size_t)e1 * 4) =
            make_float4(x10 * inv, x11 * inv, x12 * inv, x13 * inv);
    }
    out[e0] = 1.0f / (1.0f + expf(-z0));
    out[e1] = 1.0f / (1.0f + expf(-z1));
}

// ---------------- launch ----------------
extern "C" void kernel_launch(void* const* d_in, const int* in_sizes, int n_in,
                              void* d_out, int out_size) {
    const int* eidx = (const int*)d_in[1];
    const float* ea = (const float*)d_in[2];
    const float* beta = (const float*)d_in[3];
    const float* w10 = (const float*)d_in[4];
    const float* b10 = (const float*)d_in[5];
    const float* w11 = (const float*)d_in[6];
    const float* b11 = (const float*)d_in[7];
    const float* w20 = (const float*)d_in[8];
    const float* b20 = (const float*)d_in[9];
    const float* w21 = (const float*)d_in[10];
    const float* b21 = (const float*)d_in[11];
    const float* w30 = (const float*)d_in[12];
    const float* b30 = (const float*)d_in[13];
    const float* w31 = (const float*)d_in[14];
    const float* b31 = (const float*)d_in[15];
    const float* w40 = (const float*)d_in[16];
    const float* b40 = (const float*)d_in[17];
    const float* w41 = (const float*)d_in[18];
    const float* b41 = (const float*)d_in[19];
    const float* wl01 = (const float*)d_in[20];
    const float* bl01 = (const float*)d_in[21];
    const float* wl02 = (const float*)d_in[22];
    const float* bl02 = (const float*)d_in[23];
    const float* wl1 = (const float*)d_in[24];
    const float* bl1 = (const float*)d_in[25];
    const float* wl2 = (const float*)d_in[26];
    const float* bl2 = (const float*)d_in[27];
    float* out = (float*)d_out;

    float *acc1p, *acc2p, *acc3p;
    cudaGetSymbolAddress((void**)&acc1p, g_acc1);
    cudaGetSymbolAddress((void**)&acc2p, g_acc2);
    cudaGetSymbolAddress((void**)&acc3p, g_acc3);

    const int T = 256;
    const int gridNF = (NN * FF + T - 1) / T;
    const int TB = 128;
    const int gridP = (HALF_E + TB - 1) / TB;
    const int gridN = (NN + 127) / 128;

    k_init<<<gridNF, T>>>(beta, out);
    k_headfold<<<1, 192>>>(wl01, bl01, wl02, bl02, wl1, bl1, wl2, bl2);
    k_conv1<<<gridP, TB>>>(ea, eidx, w10, b10, w11, b11);

    k_node<32><<<gridN, 256>>>(acc1p, nullptr, w20, b20);
    k_edge2<<<gridP, TB>>>(ea, eidx, w20, w21, b21);

    k_node<64><<<gridN, 256>>>(acc2p, acc1p, w30, b30);
    k_edge3<<<gridP, TB>>>(eidx, w30, w31, b31);

    k_node<64><<<gridN, 256>>>(acc3p, acc2p, w40, b40);
    k_edge4<<<gridP, TB>>>(ea, eidx, w40, w41, b41, out);
}